// round 1
// baseline (speedup 1.0000x reference)
#include <cuda_runtime.h>
#include <cstdint>
#include <climits>

// p-bit Glauber sequential update, N=4096 spins, 16384 steps.
// Strategy:
//   Kernel 1 (parallel): F[j] = h[j] + dot(J[j,:], m0)  -- full matvec, warms L2 with J.
//   Kernel 2 (single CTA): window-speculative sequential dynamics.
//     - F (local fields) and m (spins) live in shared memory.
//     - Evaluate 512 future steps in parallel assuming no flip; ballot to find
//       the first step whose spin actually changes; apply that single flip
//       (rank-1 field update F += 2s * J[i,:], 16KB row from L2) and continue
//       from the step after it. Non-flip steps are free.

#define NN      4096
#define NSTEPS  16384
#define TPB     512
#define NWARPS  (TPB / 32)
#define CHUNKS  (NN / 4 / TPB)   // float4 chunks of F per thread in row update (=2)

__device__ float g_F[NN];

// ---------------------------------------------------------------------------
// Kernel 1: initial local fields F = J @ m0 + h   (one block per row)
// ---------------------------------------------------------------------------
__global__ void init_field(const float* __restrict__ J,
                           const float* __restrict__ h,
                           const float* __restrict__ m0) {
    const int row = blockIdx.x;
    const float4* __restrict__ Jr = reinterpret_cast<const float4*>(J) + (size_t)row * (NN / 4);
    const float4* __restrict__ M4 = reinterpret_cast<const float4*>(m0);

    float sum = 0.0f;
    for (int k = threadIdx.x; k < NN / 4; k += blockDim.x) {
        float4 a = Jr[k];
        float4 b = M4[k];
        sum += a.x * b.x;
        sum += a.y * b.y;
        sum += a.z * b.z;
        sum += a.w * b.w;
    }
    #pragma unroll
    for (int off = 16; off; off >>= 1)
        sum += __shfl_xor_sync(0xffffffffu, sum, off);

    __shared__ float ws[8];
    const int lane = threadIdx.x & 31;
    const int wid  = threadIdx.x >> 5;
    if (lane == 0) ws[wid] = sum;
    __syncthreads();
    if (threadIdx.x == 0) {
        float tot = 0.0f;
        #pragma unroll
        for (int w = 0; w < 8; w++) tot += ws[w];
        g_F[row] = tot + h[row];
    }
}

// ---------------------------------------------------------------------------
// Kernel 2: sequential dynamics with window speculation (single CTA)
// ---------------------------------------------------------------------------
__global__ __launch_bounds__(TPB, 1)
void pbit_dynamics(const float* __restrict__ J,
                   const float* __restrict__ m0,
                   const int*   __restrict__ idx,
                   const float* __restrict__ u,
                   float*       __restrict__ out) {
    __shared__ float F_sh[NN];                       // 16 KB local fields
    __shared__ float m_sh[NN];                       // 16 KB spins (+-1)
    __shared__ __align__(16) unsigned flip_bal[NWARPS];
    __shared__ __align__(16) unsigned sign_bal[NWARPS];

    const int tid  = threadIdx.x;
    const int lane = tid & 31;
    const int wid  = tid >> 5;

    for (int k = tid; k < NN; k += TPB) {
        F_sh[k] = g_F[k];
        m_sh[k] = m0[k];
    }
    __syncthreads();

    int t = 0;
    while (t < NSTEPS) {
        // ---- epoch 1: speculative evaluation of window [t, t+TPB) ----
        const int tt = t + tid;
        bool  flip = false;
        bool  spos = false;
        int   i_ev = 0;
        float s_ev = 1.0f;
        if (tt < NSTEPS) {
            const int   i = idx[tt];
            const float p = tanhf(F_sh[i]);
            const float r = 2.0f * u[tt] - 1.0f;     // FFMA: exact 2u, single round
            const float s = (p >= r) ? 1.0f : -1.0f; // == sign(p-r) with sign(0)->1
            spos = (s > 0.0f);
            flip = (s != m_sh[i]);
            i_ev = i;
            s_ev = s;
        }
        const unsigned fb = __ballot_sync(0xffffffffu, flip);
        const unsigned sb = __ballot_sync(0xffffffffu, spos);
        if (lane == 0) { flip_bal[wid] = fb; sign_bal[wid] = sb; }
        __syncthreads();

        // ---- epoch 2: every thread finds the first flipping position ----
        unsigned bal[NWARPS];
        {
            const uint4* fb4 = reinterpret_cast<const uint4*>(flip_bal);
            #pragma unroll
            for (int q = 0; q < NWARPS / 4; q++) {
                uint4 v = fb4[q];
                bal[q * 4 + 0] = v.x;
                bal[q * 4 + 1] = v.y;
                bal[q * 4 + 2] = v.z;
                bal[q * 4 + 3] = v.w;
            }
        }
        int f = -1;
        #pragma unroll
        for (int w = NWARPS - 1; w >= 0; w--)
            if (bal[w]) f = (w << 5) + (__ffs(bal[w]) - 1);

        if (f >= 0) {
            const int Tstep = t + f;
            const int i = idx[Tstep];                        // uniform -> L1 broadcast
            const float s = ((sign_bal[f >> 5] >> (f & 31)) & 1u) ? 1.0f : -1.0f;
            const float d = 2.0f * s;                        // delta = s - (-s)

            // rank-1 field update: F += d * J[i,:]   (16 KB row, L2 resident)
            const float4* __restrict__ Jr =
                reinterpret_cast<const float4*>(J) + (size_t)i * (NN / 4);
            float4* Fv = reinterpret_cast<float4*>(F_sh);
            #pragma unroll
            for (int c = 0; c < CHUNKS; c++) {
                const int k = tid + c * TPB;
                const float4 a = Jr[k];
                float4 fv = Fv[k];
                fv.x += a.x * d;
                fv.y += a.y * d;
                fv.z += a.z * d;
                fv.w += a.w * d;
                Fv[k] = fv;
            }
            if (tid == f) m_sh[i_ev] = s_ev;   // sole writer; readers are bar-separated
            t = Tstep + 1;
        } else {
            t += TPB;                          // whole window clean
        }
        __syncthreads();
    }

    for (int k = tid; k < NN; k += TPB)
        out[k] = m_sh[k];
}

// ---------------------------------------------------------------------------
extern "C" void kernel_launch(void* const* d_in, const int* in_sizes, int n_in,
                              void* d_out, int out_size) {
    const float* J  = (const float*)d_in[0];   // 4096*4096 f32
    const float* h  = (const float*)d_in[1];   // 4096 f32
    const float* m0 = (const float*)d_in[2];   // 4096 f32
    const int*   idx= (const int*)  d_in[3];   // 16384 i32
    const float* u  = (const float*)d_in[4];   // 16384 f32
    float* out = (float*)d_out;                // 4096 f32

    init_field<<<NN, 256>>>(J, h, m0);
    pbit_dynamics<<<1, TPB>>>(J, m0, idx, u, out);
}